// round 15
// baseline (speedup 1.0000x reference)
#include <cuda_runtime.h>
#include <cuda_bf16.h>

#define Nn   100000
#define Ee   1600000
#define F    128          // IN_F == HIDDEN
#define C2T  80           // HEADS * N_CLASSES
#define NCls 40
#define NEG  0.2f
#define EPS  1e-5f

// ---------------- scratch (static device globals; no runtime alloc) ----------
__device__ __align__(16) __nv_bfloat16 g_h1b[Nn * F];     // bf16 payload, layer 1
__device__ __align__(16) __nv_bfloat16 g_h2b[Nn * C2T];   // bf16 payload, layer 2
__device__ __align__(16) float g_out1[Nn * F];            // un-normalized accum
__device__ __align__(16) float g_out2[Nn * C2T];          // un-normalized accum

__device__ __align__(16) float g_asrc1[Nn * 2], g_adst1[Nn * 2], g_den1[Nn * 2];
__device__ __align__(16) float g_asrc2[Nn * 2], g_adst2[Nn * 2], g_den2[Nn * 2];

__device__ float g_bns[F], g_bnq[F];

// ---------------- helpers ----------------------------------------------------
__device__ __forceinline__ float lrelu(float x){ return x > 0.f ? x : NEG * x; }

__device__ __forceinline__ void red4(float* p, float a, float b, float c, float d) {
    asm volatile("red.global.add.v4.f32 [%0], {%1,%2,%3,%4};"
                 :: "l"(p), "f"(a), "f"(b), "f"(c), "f"(d) : "memory");
}
__device__ __forceinline__ void red1(float* p, float a) {
    asm volatile("red.global.add.f32 [%0], %1;"
                 :: "l"(p), "f"(a) : "memory");
}
__device__ __forceinline__ unsigned f2tf32(float f) {
    unsigned u;
    asm("cvt.rna.tf32.f32 %0, %1;" : "=r"(u) : "f"(f));
    return u;
}
__device__ __forceinline__ void mma_tf32(float* d, const unsigned* a, const unsigned* b) {
    asm volatile(
        "mma.sync.aligned.m16n8k8.row.col.f32.tf32.tf32.f32 "
        "{%0,%1,%2,%3}, {%4,%5,%6,%7}, {%8,%9}, {%0,%1,%2,%3};\n"
        : "+f"(d[0]), "+f"(d[1]), "+f"(d[2]), "+f"(d[3])
        : "r"(a[0]), "r"(a[1]), "r"(a[2]), "r"(a[3]), "r"(b[0]), "r"(b[1]));
}

// ================= GEMM1: h1 = x @ W1 (tf32); fused att dots + self-msg seed =
// block 256 thr = 8 warps; block tile 128x128; warp tile 32(M) x 64(N)
__global__ __launch_bounds__(256)
void k_gemm1(const float* __restrict__ x, const float* __restrict__ W,
             const float* __restrict__ attS, const float* __restrict__ attD) {
    __shared__ unsigned As[128][36];
    __shared__ unsigned Bs[32][136];
    int tid  = threadIdx.x;
    int lane = tid & 31, wid = tid >> 5;
    int warpM = wid & 3, warpN = wid >> 2;   // 4 x 2; warpN == head
    int g = lane >> 2, tig = lane & 3;
    int rowBase = blockIdx.x * 128;
    float acc[2][8][4] = {};

    if (blockIdx.x == 0 && tid < F) { g_bns[tid] = 0.f; g_bnq[tid] = 0.f; }

    for (int k0 = 0; k0 < F; k0 += 32) {
        #pragma unroll
        for (int l = 0; l < 4; l++) {               // A tile 128x32
            int v = tid + l * 256;
            int r = v >> 3, kq = v & 7;
            int grow = rowBase + r;
            float4 xv = make_float4(0.f, 0.f, 0.f, 0.f);
            if (grow < Nn) xv = *(const float4*)&x[grow * F + k0 + kq * 4];
            As[r][kq*4+0] = f2tf32(xv.x); As[r][kq*4+1] = f2tf32(xv.y);
            As[r][kq*4+2] = f2tf32(xv.z); As[r][kq*4+3] = f2tf32(xv.w);
        }
        #pragma unroll
        for (int l = 0; l < 4; l++) {               // B tile 32x128
            int v = tid + l * 256;
            int kk = v >> 5, nq = v & 31;
            float4 wv = *(const float4*)&W[(k0 + kk) * F + nq * 4];
            Bs[kk][nq*4+0] = f2tf32(wv.x); Bs[kk][nq*4+1] = f2tf32(wv.y);
            Bs[kk][nq*4+2] = f2tf32(wv.z); Bs[kk][nq*4+3] = f2tf32(wv.w);
        }
        __syncthreads();
        #pragma unroll
        for (int ks = 0; ks < 4; ks++) {
            unsigned a[2][4];
            #pragma unroll
            for (int mi = 0; mi < 2; mi++) {
                int r = warpM * 32 + mi * 16 + g;
                a[mi][0] = As[r    ][ks*8 + tig];
                a[mi][1] = As[r + 8][ks*8 + tig];
                a[mi][2] = As[r    ][ks*8 + tig + 4];
                a[mi][3] = As[r + 8][ks*8 + tig + 4];
            }
            #pragma unroll
            for (int ni = 0; ni < 8; ni++) {
                unsigned b[2];
                int c = warpN * 64 + ni * 8 + g;
                b[0] = Bs[ks*8 + tig    ][c];
                b[1] = Bs[ks*8 + tig + 4][c];
                mma_tf32(acc[0][ni], a[0], b);
                mma_tf32(acc[1][ni], a[1], b);
            }
        }
        __syncthreads();
    }

    // epilogue: att dots -> e_self; store h1(bf16), out1 seed = e_self*h1,
    // asrc/adst/den (non-atomic)
    #pragma unroll
    for (int mi = 0; mi < 2; mi++) {
        int r0 = rowBase + warpM * 32 + mi * 16 + g;
        int r1 = r0 + 8;
        float as0 = 0.f, ad0 = 0.f, as1 = 0.f, ad1 = 0.f;
        #pragma unroll
        for (int ni = 0; ni < 8; ni++) {
            int c0 = warpN * 64 + ni * 8 + 2 * tig;
            float sa = __ldg(&attS[c0]), sb = __ldg(&attS[c0 + 1]);
            float da = __ldg(&attD[c0]), db = __ldg(&attD[c0 + 1]);
            as0 += acc[mi][ni][0] * sa + acc[mi][ni][1] * sb;
            ad0 += acc[mi][ni][0] * da + acc[mi][ni][1] * db;
            as1 += acc[mi][ni][2] * sa + acc[mi][ni][3] * sb;
            ad1 += acc[mi][ni][2] * da + acc[mi][ni][3] * db;
        }
        as0 += __shfl_xor_sync(0xffffffff, as0, 1); as0 += __shfl_xor_sync(0xffffffff, as0, 2);
        ad0 += __shfl_xor_sync(0xffffffff, ad0, 1); ad0 += __shfl_xor_sync(0xffffffff, ad0, 2);
        as1 += __shfl_xor_sync(0xffffffff, as1, 1); as1 += __shfl_xor_sync(0xffffffff, as1, 2);
        ad1 += __shfl_xor_sync(0xffffffff, ad1, 1); ad1 += __shfl_xor_sync(0xffffffff, ad1, 2);
        float e0 = __expf(lrelu(as0 + ad0));
        float e1 = __expf(lrelu(as1 + ad1));
        #pragma unroll
        for (int ni = 0; ni < 8; ni++) {
            int c0 = warpN * 64 + ni * 8 + 2 * tig;
            if (r0 < Nn) {
                *(__nv_bfloat162*)&g_h1b[r0 * F + c0] =
                    __float22bfloat162_rn(make_float2(acc[mi][ni][0], acc[mi][ni][1]));
                *(float2*)&g_out1[r0 * F + c0] =
                    make_float2(e0 * acc[mi][ni][0], e0 * acc[mi][ni][1]);
            }
            if (r1 < Nn) {
                *(__nv_bfloat162*)&g_h1b[r1 * F + c0] =
                    __float22bfloat162_rn(make_float2(acc[mi][ni][2], acc[mi][ni][3]));
                *(float2*)&g_out1[r1 * F + c0] =
                    make_float2(e1 * acc[mi][ni][2], e1 * acc[mi][ni][3]);
            }
        }
        if (tig == 0) {
            if (r0 < Nn) { g_asrc1[r0*2+warpN] = as0; g_adst1[r0*2+warpN] = ad0; g_den1[r0*2+warpN] = e0; }
            if (r1 < Nn) { g_asrc1[r1*2+warpN] = as1; g_adst1[r1*2+warpN] = ad1; g_den1[r1*2+warpN] = e1; }
        }
    }
}

// ======= msg1: warp/edge; per-lane exp; bf16 gather; fused den accumulation ==
// Lanes 0..15 = head0, 16..31 = head1. Lane 0 / lane 16 already hold w for
// their head; they alone fire a scalar RED into den (no shuffle, no chain).
__global__ __launch_bounds__(256)
void k_msg1(const int* __restrict__ src, const int* __restrict__ dst) {
    int warp = (blockIdx.x * blockDim.x + threadIdx.x) >> 5;
    int lane = threadIdx.x & 31;
    if (warp >= Ee) return;
    int s = __ldg(&src[warp]);
    int d = __ldg(&dst[warp]);
    int h = lane >> 4;
    float w = __expf(lrelu(g_asrc1[s * 2 + h] + g_adst1[d * 2 + h]));
    if ((lane & 15) == 0) red1(&g_den1[d * 2 + h], w);
    uint2 p = *(const uint2*)((const char*)g_h1b + (size_t)s * 256 + lane * 8);
    float2 f0 = __bfloat1622float2(*(__nv_bfloat162*)&p.x);
    float2 f1 = __bfloat1622float2(*(__nv_bfloat162*)&p.y);
    red4(&g_out1[d * F + lane * 4], f0.x * w, f0.y * w, f1.x * w, f1.y * w);
}

// ----- BN stats over normalized out1; also den1 -> 1/den1 (fused rinv) -------
// Each block owns rows [i0, i0+64); inverts its own den entries (disjoint,
// race-free) and caches them in smem for the stats loop.
__global__ __launch_bounds__(128)
void k_stats() {
    __shared__ float sinv[128];             // 64 rows x 2 heads
    int c = threadIdx.x;                    // 128 threads, one per feature
    int i0 = blockIdx.x * 64;
    int head = c >> 6;
    int t = i0 * 2 + c;                     // den index covered by this thread
    if (t < 2 * Nn) {
        float inv = 1.0f / g_den1[t];
        g_den1[t] = inv;                    // write back for GEMM2's A-load
        sinv[c] = inv;
    }
    __syncthreads();
    float s = 0.f, q = 0.f;
    for (int r = 0; r < 64; r++) {
        int i = i0 + r;
        if (i >= Nn) break;
        float v = g_out1[i * F + c] * sinv[r * 2 + head];
        s += v; q += v * v;
    }
    atomicAdd(&g_bns[c], s);
    atomicAdd(&g_bnq[c], q);
}

// ================= GEMM2: h2 = BN(out1*invden) @ W2 (tf32) ===================
// BN finalize fused into prologue (each block recomputes scale/shift — trivial).
// block tile 128x80; warp tile 32(M) x 40(N); warpN == head
__global__ __launch_bounds__(256)
void k_gemm2(const float* __restrict__ W, const float* __restrict__ attS,
             const float* __restrict__ attD,
             const float* __restrict__ gamma, const float* __restrict__ beta) {
    __shared__ unsigned As[128][36];
    __shared__ unsigned Bs[32][88];
    __shared__ float sc[F], sh[F];
    int tid  = threadIdx.x;
    int lane = tid & 31, wid = tid >> 5;
    int warpM = wid & 3, warpN = wid >> 2;
    int g = lane >> 2, tig = lane & 3;
    int rowBase = blockIdx.x * 128;
    float acc[2][5][4] = {};

    if (tid < F) {                          // fused BN finalize
        float m = g_bns[tid] * (1.0f / (float)Nn);
        float v = g_bnq[tid] * (1.0f / (float)Nn) - m * m;
        float scv = __ldg(&gamma[tid]) * rsqrtf(v + EPS);
        sc[tid] = scv;
        sh[tid] = __ldg(&beta[tid]) - m * scv;
    }
    __syncthreads();

    for (int k0 = 0; k0 < F; k0 += 32) {
        #pragma unroll
        for (int l = 0; l < 4; l++) {               // A tile: normalize + BN at load
            int v = tid + l * 256;
            int r = v >> 3, kq = v & 7;
            int grow = rowBase + r;
            int kc = k0 + kq * 4;
            float4 xv = make_float4(0.f, 0.f, 0.f, 0.f);
            float inv = 0.f;
            if (grow < Nn) {
                xv  = *(const float4*)&g_out1[grow * F + kc];
                inv = g_den1[grow * 2 + (kc >= 64)];
            }
            As[r][kq*4+0] = f2tf32(xv.x * inv * sc[kc+0] + sh[kc+0]);
            As[r][kq*4+1] = f2tf32(xv.y * inv * sc[kc+1] + sh[kc+1]);
            As[r][kq*4+2] = f2tf32(xv.z * inv * sc[kc+2] + sh[kc+2]);
            As[r][kq*4+3] = f2tf32(xv.w * inv * sc[kc+3] + sh[kc+3]);
        }
        #pragma unroll
        for (int l = 0; l < 3; l++) {               // B tile 32x80 = 640 float4
            int v = tid + l * 256;
            if (v < 640) {
                int kk = v / 20, nq = v % 20;
                float4 wv = *(const float4*)&W[(k0 + kk) * C2T + nq * 4];
                Bs[kk][nq*4+0] = f2tf32(wv.x); Bs[kk][nq*4+1] = f2tf32(wv.y);
                Bs[kk][nq*4+2] = f2tf32(wv.z); Bs[kk][nq*4+3] = f2tf32(wv.w);
            }
        }
        __syncthreads();
        #pragma unroll
        for (int ks = 0; ks < 4; ks++) {
            unsigned a[2][4];
            #pragma unroll
            for (int mi = 0; mi < 2; mi++) {
                int r = warpM * 32 + mi * 16 + g;
                a[mi][0] = As[r    ][ks*8 + tig];
                a[mi][1] = As[r + 8][ks*8 + tig];
                a[mi][2] = As[r    ][ks*8 + tig + 4];
                a[mi][3] = As[r + 8][ks*8 + tig + 4];
            }
            #pragma unroll
            for (int ni = 0; ni < 5; ni++) {
                unsigned b[2];
                int c = warpN * 40 + ni * 8 + g;
                b[0] = Bs[ks*8 + tig    ][c];
                b[1] = Bs[ks*8 + tig + 4][c];
                mma_tf32(acc[0][ni], a[0], b);
                mma_tf32(acc[1][ni], a[1], b);
            }
        }
        __syncthreads();
    }

    #pragma unroll
    for (int mi = 0; mi < 2; mi++) {
        int r0 = rowBase + warpM * 32 + mi * 16 + g;
        int r1 = r0 + 8;
        float as0 = 0.f, ad0 = 0.f, as1 = 0.f, ad1 = 0.f;
        #pragma unroll
        for (int ni = 0; ni < 5; ni++) {
            int c0 = warpN * 40 + ni * 8 + 2 * tig;
            float sa = __ldg(&attS[c0]), sb = __ldg(&attS[c0 + 1]);
            float da = __ldg(&attD[c0]), db = __ldg(&attD[c0 + 1]);
            as0 += acc[mi][ni][0] * sa + acc[mi][ni][1] * sb;
            ad0 += acc[mi][ni][0] * da + acc[mi][ni][1] * db;
            as1 += acc[mi][ni][2] * sa + acc[mi][ni][3] * sb;
            ad1 += acc[mi][ni][2] * da + acc[mi][ni][3] * db;
        }
        as0 += __shfl_xor_sync(0xffffffff, as0, 1); as0 += __shfl_xor_sync(0xffffffff, as0, 2);
        ad0 += __shfl_xor_sync(0xffffffff, ad0, 1); ad0 += __shfl_xor_sync(0xffffffff, ad0, 2);
        as1 += __shfl_xor_sync(0xffffffff, as1, 1); as1 += __shfl_xor_sync(0xffffffff, as1, 2);
        ad1 += __shfl_xor_sync(0xffffffff, ad1, 1); ad1 += __shfl_xor_sync(0xffffffff, ad1, 2);
        float e0 = __expf(lrelu(as0 + ad0));
        float e1 = __expf(lrelu(as1 + ad1));
        #pragma unroll
        for (int ni = 0; ni < 5; ni++) {
            int c0 = warpN * 40 + ni * 8 + 2 * tig;
            if (r0 < Nn) {
                *(__nv_bfloat162*)&g_h2b[r0 * C2T + c0] =
                    __float22bfloat162_rn(make_float2(acc[mi][ni][0], acc[mi][ni][1]));
                *(float2*)&g_out2[r0 * C2T + c0] =
                    make_float2(e0 * acc[mi][ni][0], e0 * acc[mi][ni][1]);
            }
            if (r1 < Nn) {
                *(__nv_bfloat162*)&g_h2b[r1 * C2T + c0] =
                    __float22bfloat162_rn(make_float2(acc[mi][ni][2], acc[mi][ni][3]));
                *(float2*)&g_out2[r1 * C2T + c0] =
                    make_float2(e1 * acc[mi][ni][2], e1 * acc[mi][ni][3]);
            }
        }
        if (tig == 0) {
            if (r0 < Nn) { g_asrc2[r0*2+warpN] = as0; g_adst2[r0*2+warpN] = ad0; g_den2[r0*2+warpN] = e0; }
            if (r1 < Nn) { g_asrc2[r1*2+warpN] = as1; g_adst2[r1*2+warpN] = ad1; g_den2[r1*2+warpN] = e1; }
        }
    }
}

// ======= msg2: warp/edge (20 active lanes); per-lane exp; bf16 gather;
//         fused den accumulation via q==0 lanes (lanes 0 and 10) =============
__global__ __launch_bounds__(256)
void k_msg2(const int* __restrict__ src, const int* __restrict__ dst) {
    int warp = (blockIdx.x * blockDim.x + threadIdx.x) >> 5;
    int lane = threadIdx.x & 31;
    if (warp >= Ee || lane >= 20) return;
    int s = __ldg(&src[warp]);
    int d = __ldg(&dst[warp]);
    int h = lane >= 10;
    int q = lane - h * 10;
    float w = __expf(lrelu(g_asrc2[s * 2 + h] + g_adst2[d * 2 + h]));
    if (q == 0) red1(&g_den2[d * 2 + h], w);
    uint2 p = *(const uint2*)((const char*)g_h2b + (size_t)s * 160 + h * 80 + q * 8);
    float2 f0 = __bfloat1622float2(*(__nv_bfloat162*)&p.x);
    float2 f1 = __bfloat1622float2(*(__nv_bfloat162*)&p.y);
    red4(&g_out2[d * C2T + h * 40 + q * 4], f0.x * w, f0.y * w, f1.x * w, f1.y * w);
}

// ------- final: normalize + head mean + bias + log_softmax -------------------
__global__ __launch_bounds__(256)
void k_final2(const float* __restrict__ b2, float* __restrict__ out) {
    int i = (blockIdx.x * blockDim.x + threadIdx.x) >> 5;
    int lane = threadIdx.x & 31;
    if (i >= Nn) return;
    float2 dn = *(const float2*)&g_den2[i * 2];
    float inv0 = 0.5f / dn.x;
    float inv1 = 0.5f / dn.y;
    const float* o = &g_out2[i * C2T];

    int c = lane;                            // classes 0..31
    float va = o[c] * inv0 + o[40 + c] * inv1 + __ldg(&b2[c]);
    float vb = -1e30f;
    if (lane < 8) {
        int cb = lane + 32;
        vb = o[cb] * inv0 + o[40 + cb] * inv1 + __ldg(&b2[cb]);
    }
    float m = fmaxf(va, vb);
    #pragma unroll
    for (int off = 16; off; off >>= 1) m = fmaxf(m, __shfl_xor_sync(0xffffffff, m, off));
    float s = __expf(va - m) + (lane < 8 ? __expf(vb - m) : 0.f);
    #pragma unroll
    for (int off = 16; off; off >>= 1) s += __shfl_xor_sync(0xffffffff, s, off);
    float lg = m + __logf(s);
    out[i * NCls + lane] = va - lg;
    if (lane < 8) out[i * NCls + 32 + lane] = vb - lg;
}

// ---------------- launch -----------------------------------------------------
extern "C" void kernel_launch(void* const* d_in, const int* in_sizes, int n_in,
                              void* d_out, int out_size) {
    const float* x     = (const float*)d_in[0];
    const int*   ei    = (const int*)  d_in[1];
    const float* W1    = (const float*)d_in[2];
    const float* as1   = (const float*)d_in[3];
    const float* ad1   = (const float*)d_in[4];
    // d_in[5] = b1 (cancels inside BatchNorm — unused)
    const float* gamma = (const float*)d_in[6];
    const float* beta  = (const float*)d_in[7];
    const float* W2    = (const float*)d_in[8];
    const float* as2   = (const float*)d_in[9];
    const float* ad2   = (const float*)d_in[10];
    const float* b2    = (const float*)d_in[11];
    float* out = (float*)d_out;

    const int* src = ei;
    const int* dst = ei + Ee;

    const int TB = 256;
    int gG  = (Nn + 127) / 128;
    int gEw = (Ee * 32 + TB - 1) / TB;       // warp per edge

    // ---- layer 1 ----
    k_gemm1<<<gG, TB>>>(x, W1, as1, ad1);
    k_msg1<<<gEw, TB>>>(src, dst);           // fused: den1 += exp
    k_stats<<<(Nn + 63) / 64, 128>>>();      // fused: rinv(den1) + BN stats
    // ---- layer 2 ----
    k_gemm2<<<gG, TB>>>(W2, as2, ad2, gamma, beta);
    k_msg2<<<gEw, TB>>>(src, dst);           // fused: den2 += exp
    k_final2<<<(Nn * 32 + TB - 1) / TB, TB>>>(b2, out);
}

// round 16
// speedup vs baseline: 1.9335x; 1.9335x over previous
#include <cuda_runtime.h>
#include <cuda_bf16.h>

#define Nn   100000
#define Ee   1600000
#define F    128          // IN_F == HIDDEN
#define C2T  80           // HEADS * N_CLASSES
#define NCls 40
#define NEG  0.2f
#define EPS  1e-5f
#define SCB  ((Nn + 511) / 512)   // scan blocks = 196

// ---------------- scratch (static device globals; no runtime alloc) ----------
__device__ __align__(16) __nv_bfloat16 g_h1b[Nn * F];     // bf16 payload, layer 1
__device__ __align__(16) __nv_bfloat16 g_h2b[Nn * C2T];   // bf16 payload, layer 2
__device__ __align__(16) float g_out1[Nn * F];            // accum (seeded by gemm)
__device__ __align__(16) float g_out2[Nn * C2T];

__device__ __align__(16) float g_asrc1[Nn * 2], g_adst1[Nn * 2], g_den1[Nn * 2];
__device__ __align__(16) float g_asrc2[Nn * 2], g_adst2[Nn * 2], g_den2[Nn * 2];

__device__ float g_bns[F], g_bnq[F];

// CSR scratch (built once per launch, reused by both layers)
__device__ int g_cnt[Nn];
__device__ int g_rowptr[Nn + 1];
__device__ int g_cur[Nn];
__device__ int g_bsum[SCB];
__device__ int g_csrc[Ee];

// ---------------- helpers ----------------------------------------------------
__device__ __forceinline__ float lrelu(float x){ return x > 0.f ? x : NEG * x; }

__device__ __forceinline__ unsigned f2tf32(float f) {
    unsigned u;
    asm("cvt.rna.tf32.f32 %0, %1;" : "=r"(u) : "f"(f));
    return u;
}
__device__ __forceinline__ void mma_tf32(float* d, const unsigned* a, const unsigned* b) {
    asm volatile(
        "mma.sync.aligned.m16n8k8.row.col.f32.tf32.tf32.f32 "
        "{%0,%1,%2,%3}, {%4,%5,%6,%7}, {%8,%9}, {%0,%1,%2,%3};\n"
        : "+f"(d[0]), "+f"(d[1]), "+f"(d[2]), "+f"(d[3])
        : "r"(a[0]), "r"(a[1]), "r"(a[2]), "r"(a[3]), "r"(b[0]), "r"(b[1]));
}

// ================= GEMM1: h1 = x @ W1 (tf32); fused att dots + self-msg seed =
__global__ __launch_bounds__(256)
void k_gemm1(const float* __restrict__ x, const float* __restrict__ W,
             const float* __restrict__ attS, const float* __restrict__ attD) {
    __shared__ unsigned As[128][36];
    __shared__ unsigned Bs[32][136];
    int tid  = threadIdx.x;
    int lane = tid & 31, wid = tid >> 5;
    int warpM = wid & 3, warpN = wid >> 2;   // 4 x 2; warpN == head
    int g = lane >> 2, tig = lane & 3;
    int rowBase = blockIdx.x * 128;
    float acc[2][8][4] = {};

    if (blockIdx.x == 0 && tid < F) { g_bns[tid] = 0.f; g_bnq[tid] = 0.f; }
    { int gt = blockIdx.x * 256 + tid; if (gt < Nn) g_cnt[gt] = 0; }  // zero CSR hist

    for (int k0 = 0; k0 < F; k0 += 32) {
        #pragma unroll
        for (int l = 0; l < 4; l++) {               // A tile 128x32
            int v = tid + l * 256;
            int r = v >> 3, kq = v & 7;
            int grow = rowBase + r;
            float4 xv = make_float4(0.f, 0.f, 0.f, 0.f);
            if (grow < Nn) xv = *(const float4*)&x[grow * F + k0 + kq * 4];
            As[r][kq*4+0] = f2tf32(xv.x); As[r][kq*4+1] = f2tf32(xv.y);
            As[r][kq*4+2] = f2tf32(xv.z); As[r][kq*4+3] = f2tf32(xv.w);
        }
        #pragma unroll
        for (int l = 0; l < 4; l++) {               // B tile 32x128
            int v = tid + l * 256;
            int kk = v >> 5, nq = v & 31;
            float4 wv = *(const float4*)&W[(k0 + kk) * F + nq * 4];
            Bs[kk][nq*4+0] = f2tf32(wv.x); Bs[kk][nq*4+1] = f2tf32(wv.y);
            Bs[kk][nq*4+2] = f2tf32(wv.z); Bs[kk][nq*4+3] = f2tf32(wv.w);
        }
        __syncthreads();
        #pragma unroll
        for (int ks = 0; ks < 4; ks++) {
            unsigned a[2][4];
            #pragma unroll
            for (int mi = 0; mi < 2; mi++) {
                int r = warpM * 32 + mi * 16 + g;
                a[mi][0] = As[r    ][ks*8 + tig];
                a[mi][1] = As[r + 8][ks*8 + tig];
                a[mi][2] = As[r    ][ks*8 + tig + 4];
                a[mi][3] = As[r + 8][ks*8 + tig + 4];
            }
            #pragma unroll
            for (int ni = 0; ni < 8; ni++) {
                unsigned b[2];
                int c = warpN * 64 + ni * 8 + g;
                b[0] = Bs[ks*8 + tig    ][c];
                b[1] = Bs[ks*8 + tig + 4][c];
                mma_tf32(acc[0][ni], a[0], b);
                mma_tf32(acc[1][ni], a[1], b);
            }
        }
        __syncthreads();
    }

    #pragma unroll
    for (int mi = 0; mi < 2; mi++) {
        int r0 = rowBase + warpM * 32 + mi * 16 + g;
        int r1 = r0 + 8;
        float as0 = 0.f, ad0 = 0.f, as1 = 0.f, ad1 = 0.f;
        #pragma unroll
        for (int ni = 0; ni < 8; ni++) {
            int c0 = warpN * 64 + ni * 8 + 2 * tig;
            float sa = __ldg(&attS[c0]), sb = __ldg(&attS[c0 + 1]);
            float da = __ldg(&attD[c0]), db = __ldg(&attD[c0 + 1]);
            as0 += acc[mi][ni][0] * sa + acc[mi][ni][1] * sb;
            ad0 += acc[mi][ni][0] * da + acc[mi][ni][1] * db;
            as1 += acc[mi][ni][2] * sa + acc[mi][ni][3] * sb;
            ad1 += acc[mi][ni][2] * da + acc[mi][ni][3] * db;
        }
        as0 += __shfl_xor_sync(0xffffffff, as0, 1); as0 += __shfl_xor_sync(0xffffffff, as0, 2);
        ad0 += __shfl_xor_sync(0xffffffff, ad0, 1); ad0 += __shfl_xor_sync(0xffffffff, ad0, 2);
        as1 += __shfl_xor_sync(0xffffffff, as1, 1); as1 += __shfl_xor_sync(0xffffffff, as1, 2);
        ad1 += __shfl_xor_sync(0xffffffff, ad1, 1); ad1 += __shfl_xor_sync(0xffffffff, ad1, 2);
        float e0 = __expf(lrelu(as0 + ad0));
        float e1 = __expf(lrelu(as1 + ad1));
        #pragma unroll
        for (int ni = 0; ni < 8; ni++) {
            int c0 = warpN * 64 + ni * 8 + 2 * tig;
            if (r0 < Nn) {
                *(__nv_bfloat162*)&g_h1b[r0 * F + c0] =
                    __float22bfloat162_rn(make_float2(acc[mi][ni][0], acc[mi][ni][1]));
                *(float2*)&g_out1[r0 * F + c0] =
                    make_float2(e0 * acc[mi][ni][0], e0 * acc[mi][ni][1]);
            }
            if (r1 < Nn) {
                *(__nv_bfloat162*)&g_h1b[r1 * F + c0] =
                    __float22bfloat162_rn(make_float2(acc[mi][ni][2], acc[mi][ni][3]));
                *(float2*)&g_out1[r1 * F + c0] =
                    make_float2(e1 * acc[mi][ni][2], e1 * acc[mi][ni][3]);
            }
        }
        if (tig == 0) {
            if (r0 < Nn) { g_asrc1[r0*2+warpN] = as0; g_adst1[r0*2+warpN] = ad0; g_den1[r0*2+warpN] = e0; }
            if (r1 < Nn) { g_asrc1[r1*2+warpN] = as1; g_adst1[r1*2+warpN] = ad1; g_den1[r1*2+warpN] = e1; }
        }
    }
}

// ================= CSR build =================================================
__global__ __launch_bounds__(256)
void k_hist(const int* __restrict__ dst) {
    int e = blockIdx.x * blockDim.x + threadIdx.x;
    if (e < Ee) atomicAdd(&g_cnt[__ldg(&dst[e])], 1);
}

__global__ __launch_bounds__(512)
void k_scan_block() {                        // per-block exclusive scan of g_cnt
    __shared__ int sh[512];
    int t = threadIdx.x;
    int i = blockIdx.x * 512 + t;
    int v = (i < Nn) ? g_cnt[i] : 0;
    sh[t] = v;
    __syncthreads();
    #pragma unroll
    for (int off = 1; off < 512; off <<= 1) {
        int xv = (t >= off) ? sh[t - off] : 0;
        __syncthreads();
        sh[t] += xv;
        __syncthreads();
    }
    if (i < Nn) g_rowptr[i] = sh[t] - v;     // local exclusive
    if (t == 511) g_bsum[blockIdx.x] = sh[511];
}

__global__ void k_scan_top() {               // scan 196 block sums (1 thread)
    if (threadIdx.x == 0) {
        int run = 0;
        for (int b = 0; b < SCB; b++) { int t = g_bsum[b]; g_bsum[b] = run; run += t; }
        g_rowptr[Nn] = Ee;
    }
}

__global__ __launch_bounds__(512)
void k_scan_add() {                          // add block offsets; init cursors
    int i = blockIdx.x * 512 + threadIdx.x;
    if (i < Nn) {
        int v = g_rowptr[i] + g_bsum[blockIdx.x];
        g_rowptr[i] = v;
        g_cur[i] = v;
    }
}

__global__ __launch_bounds__(256)
void k_fill(const int* __restrict__ src, const int* __restrict__ dst) {
    int e = blockIdx.x * blockDim.x + threadIdx.x;
    if (e >= Ee) return;
    int d = __ldg(&dst[e]);
    int pos = atomicAdd(&g_cur[d], 1);
    g_csrc[pos] = __ldg(&src[e]);
}

// ======= msg1 (CSR): warp per dst; register accum; zero atomics ==============
__global__ __launch_bounds__(256)
void k_msg1() {
    int node = (blockIdx.x * blockDim.x + threadIdx.x) >> 5;
    int lane = threadIdx.x & 31;
    if (node >= Nn) return;
    int start = __ldg(&g_rowptr[node]);
    int end   = __ldg(&g_rowptr[node + 1]);
    int h = lane >> 4;
    float adh = g_adst1[node * 2 + h];
    float4 acc = *(const float4*)&g_out1[node * F + lane * 4];   // seed e_self*h
    float den = g_den1[node * 2 + h];                            // seed e_self
    #pragma unroll 2
    for (int j = start; j < end; j++) {
        int s = __ldg(&g_csrc[j]);
        float w = __expf(lrelu(__ldg(&g_asrc1[s * 2 + h]) + adh));
        den += w;
        uint2 p = *(const uint2*)((const char*)g_h1b + (size_t)s * 256 + lane * 8);
        float2 f0 = __bfloat1622float2(*(__nv_bfloat162*)&p.x);
        float2 f1 = __bfloat1622float2(*(__nv_bfloat162*)&p.y);
        acc.x += f0.x * w; acc.y += f0.y * w;
        acc.z += f1.x * w; acc.w += f1.y * w;
    }
    *(float4*)&g_out1[node * F + lane * 4] = acc;
    if ((lane & 15) == 0) g_den1[node * 2 + h] = den;            // plain store
}

// ----- BN stats over normalized out1; den1 -> 1/den1 (fused rinv) ------------
__global__ __launch_bounds__(128)
void k_stats() {
    __shared__ float sinv[128];             // 64 rows x 2 heads
    int c = threadIdx.x;
    int i0 = blockIdx.x * 64;
    int head = c >> 6;
    int t = i0 * 2 + c;
    if (t < 2 * Nn) {
        float inv = 1.0f / g_den1[t];
        g_den1[t] = inv;
        sinv[c] = inv;
    }
    __syncthreads();
    float s = 0.f, q = 0.f;
    for (int r = 0; r < 64; r++) {
        int i = i0 + r;
        if (i >= Nn) break;
        float v = g_out1[i * F + c] * sinv[r * 2 + head];
        s += v; q += v * v;
    }
    atomicAdd(&g_bns[c], s);
    atomicAdd(&g_bnq[c], q);
}

// ================= GEMM2: h2 = BN(out1*invden) @ W2 (tf32) ===================
__global__ __launch_bounds__(256)
void k_gemm2(const float* __restrict__ W, const float* __restrict__ attS,
             const float* __restrict__ attD,
             const float* __restrict__ gamma, const float* __restrict__ beta) {
    __shared__ unsigned As[128][36];
    __shared__ unsigned Bs[32][88];
    __shared__ float sc[F], sh[F];
    int tid  = threadIdx.x;
    int lane = tid & 31, wid = tid >> 5;
    int warpM = wid & 3, warpN = wid >> 2;
    int g = lane >> 2, tig = lane & 3;
    int rowBase = blockIdx.x * 128;
    float acc[2][5][4] = {};

    if (tid < F) {                          // fused BN finalize
        float m = g_bns[tid] * (1.0f / (float)Nn);
        float v = g_bnq[tid] * (1.0f / (float)Nn) - m * m;
        float scv = __ldg(&gamma[tid]) * rsqrtf(v + EPS);
        sc[tid] = scv;
        sh[tid] = __ldg(&beta[tid]) - m * scv;
    }
    __syncthreads();

    for (int k0 = 0; k0 < F; k0 += 32) {
        #pragma unroll
        for (int l = 0; l < 4; l++) {               // A tile: normalize + BN at load
            int v = tid + l * 256;
            int r = v >> 3, kq = v & 7;
            int grow = rowBase + r;
            int kc = k0 + kq * 4;
            float4 xv = make_float4(0.f, 0.f, 0.f, 0.f);
            float inv = 0.f;
            if (grow < Nn) {
                xv  = *(const float4*)&g_out1[grow * F + kc];
                inv = g_den1[grow * 2 + (kc >= 64)];
            }
            As[r][kq*4+0] = f2tf32(xv.x * inv * sc[kc+0] + sh[kc+0]);
            As[r][kq*4+1] = f2tf32(xv.y * inv * sc[kc+1] + sh[kc+1]);
            As[r][kq*4+2] = f2tf32(xv.z * inv * sc[kc+2] + sh[kc+2]);
            As[r][kq*4+3] = f2tf32(xv.w * inv * sc[kc+3] + sh[kc+3]);
        }
        #pragma unroll
        for (int l = 0; l < 3; l++) {               // B tile 32x80 = 640 float4
            int v = tid + l * 256;
            if (v < 640) {
                int kk = v / 20, nq = v % 20;
                float4 wv = *(const float4*)&W[(k0 + kk) * C2T + nq * 4];
                Bs[kk][nq*4+0] = f2tf32(wv.x); Bs[kk][nq*4+1] = f2tf32(wv.y);
                Bs[kk][nq*4+2] = f2tf32(wv.z); Bs[kk][nq*4+3] = f2tf32(wv.w);
            }
        }
        __syncthreads();
        #pragma unroll
        for (int ks = 0; ks < 4; ks++) {
            unsigned a[2][4];
            #pragma unroll
            for (int mi = 0; mi < 2; mi++) {
                int r = warpM * 32 + mi * 16 + g;
                a[mi][0] = As[r    ][ks*8 + tig];
                a[mi][1] = As[r + 8][ks*8 + tig];
                a[mi][2] = As[r    ][ks*8 + tig + 4];
                a[mi][3] = As[r + 8][ks*8 + tig + 4];
            }
            #pragma unroll
            for (int ni = 0; ni < 5; ni++) {
                unsigned b[2];
                int c = warpN * 40 + ni * 8 + g;
                b[0] = Bs[ks*8 + tig    ][c];
                b[1] = Bs[ks*8 + tig + 4][c];
                mma_tf32(acc[0][ni], a[0], b);
                mma_tf32(acc[1][ni], a[1], b);
            }
        }
        __syncthreads();
    }

    #pragma unroll
    for (int mi = 0; mi < 2; mi++) {
        int r0 = rowBase + warpM * 32 + mi * 16 + g;
        int r1 = r0 + 8;
        float as0 = 0.f, ad0 = 0.f, as1 = 0.f, ad1 = 0.f;
        #pragma unroll
        for (int ni = 0; ni < 5; ni++) {
            int c0 = warpN * 40 + ni * 8 + 2 * tig;
            float sa = __ldg(&attS[c0]), sb = __ldg(&attS[c0 + 1]);
            float da = __ldg(&attD[c0]), db = __ldg(&attD[c0 + 1]);
            as0 += acc[mi][ni][0] * sa + acc[mi][ni][1] * sb;
            ad0 += acc[mi][ni][0] * da + acc[mi][ni][1] * db;
            as1 += acc[mi][ni][2] * sa + acc[mi][ni][3] * sb;
            ad1 += acc[mi][ni][2] * da + acc[mi][ni][3] * db;
        }
        as0 += __shfl_xor_sync(0xffffffff, as0, 1); as0 += __shfl_xor_sync(0xffffffff, as0, 2);
        ad0 += __shfl_xor_sync(0xffffffff, ad0, 1); ad0 += __shfl_xor_sync(0xffffffff, ad0, 2);
        as1 += __shfl_xor_sync(0xffffffff, as1, 1); as1 += __shfl_xor_sync(0xffffffff, as1, 2);
        ad1 += __shfl_xor_sync(0xffffffff, ad1, 1); ad1 += __shfl_xor_sync(0xffffffff, ad1, 2);
        float e0 = __expf(lrelu(as0 + ad0));
        float e1 = __expf(lrelu(as1 + ad1));
        #pragma unroll
        for (int ni = 0; ni < 5; ni++) {
            int c0 = warpN * 40 + ni * 8 + 2 * tig;
            if (r0 < Nn) {
                *(__nv_bfloat162*)&g_h2b[r0 * C2T + c0] =
                    __float22bfloat162_rn(make_float2(acc[mi][ni][0], acc[mi][ni][1]));
                *(float2*)&g_out2[r0 * C2T + c0] =
                    make_float2(e0 * acc[mi][ni][0], e0 * acc[mi][ni][1]);
            }
            if (r1 < Nn) {
                *(__nv_bfloat162*)&g_h2b[r1 * C2T + c0] =
                    __float22bfloat162_rn(make_float2(acc[mi][ni][2], acc[mi][ni][3]));
                *(float2*)&g_out2[r1 * C2T + c0] =
                    make_float2(e1 * acc[mi][ni][2], e1 * acc[mi][ni][3]);
            }
        }
        if (tig == 0) {
            if (r0 < Nn) { g_asrc2[r0*2+warpN] = as0; g_adst2[r0*2+warpN] = ad0; g_den2[r0*2+warpN] = e0; }
            if (r1 < Nn) { g_asrc2[r1*2+warpN] = as1; g_adst2[r1*2+warpN] = ad1; g_den2[r1*2+warpN] = e1; }
        }
    }
}

// ======= msg2 (CSR): warp per dst; 20 active lanes; zero atomics =============
__global__ __launch_bounds__(256)
void k_msg2() {
    int node = (blockIdx.x * blockDim.x + threadIdx.x) >> 5;
    int lane = threadIdx.x & 31;
    if (node >= Nn || lane >= 20) return;
    int start = __ldg(&g_rowptr[node]);
    int end   = __ldg(&g_rowptr[node + 1]);
    int h = lane >= 10;
    int q = lane - h * 10;
    float adh = g_adst2[node * 2 + h];
    float4 acc = *(const float4*)&g_out2[node * C2T + h * 40 + q * 4];  // seed
    float den = g_den2[node * 2 + h];                                  // seed
    #pragma unroll 2
    for (int j = start; j < end; j++) {
        int s = __ldg(&g_csrc[j]);
        float w = __expf(lrelu(__ldg(&g_asrc2[s * 2 + h]) + adh));
        den += w;
        uint2 p = *(const uint2*)((const char*)g_h2b + (size_t)s * 160 + h * 80 + q * 8);
        float2 f0 = __bfloat1622float2(*(__nv_bfloat162*)&p.x);
        float2 f1 = __bfloat1622float2(*(__nv_bfloat162*)&p.y);
        acc.x += f0.x * w; acc.y += f0.y * w;
        acc.z += f1.x * w; acc.w += f1.y * w;
    }
    *(float4*)&g_out2[node * C2T + h * 40 + q * 4] = acc;
    if (q == 0) g_den2[node * 2 + h] = den;                            // plain store
}

// ------- final: normalize + head mean + bias + log_softmax -------------------
__global__ __launch_bounds__(256)
void k_final2(const float* __restrict__ b2, float* __restrict__ out) {
    int i = (blockIdx.x * blockDim.x + threadIdx.x) >> 5;
    int lane = threadIdx.x & 31;
    if (i >= Nn) return;
    float2 dn = *(const float2*)&g_den2[i * 2];
    float inv0 = 0.5f / dn.x;
    float inv1 = 0.5f / dn.y;
    const float* o = &g_out2[i * C2T];

    int c = lane;                            // classes 0..31
    float va = o[c] * inv0 + o[40 + c] * inv1 + __ldg(&b2[c]);
    float vb = -1e30f;
    if (lane < 8) {
        int cb = lane + 32;
        vb = o[cb] * inv0 + o[40 + cb] * inv1 + __ldg(&b2[cb]);
    }
    float m = fmaxf(va, vb);
    #pragma unroll
    for (int off = 16; off; off >>= 1) m = fmaxf(m, __shfl_xor_sync(0xffffffff, m, off));
    float s = __expf(va - m) + (lane < 8 ? __expf(vb - m) : 0.f);
    #pragma unroll
    for (int off = 16; off; off >>= 1) s += __shfl_xor_sync(0xffffffff, s, off);
    float lg = m + __logf(s);
    out[i * NCls + lane] = va - lg;
    if (lane < 8) out[i * NCls + 32 + lane] = vb - lg;
}

// ---------------- launch -----------------------------------------------------
extern "C" void kernel_launch(void* const* d_in, const int* in_sizes, int n_in,
                              void* d_out, int out_size) {
    const float* x     = (const float*)d_in[0];
    const int*   ei    = (const int*)  d_in[1];
    const float* W1    = (const float*)d_in[2];
    const float* as1   = (const float*)d_in[3];
    const float* ad1   = (const float*)d_in[4];
    // d_in[5] = b1 (cancels inside BatchNorm — unused)
    const float* gamma = (const float*)d_in[6];
    const float* beta  = (const float*)d_in[7];
    const float* W2    = (const float*)d_in[8];
    const float* as2   = (const float*)d_in[9];
    const float* ad2   = (const float*)d_in[10];
    const float* b2    = (const float*)d_in[11];
    float* out = (float*)d_out;

    const int* src = ei;
    const int* dst = ei + Ee;

    const int TB = 256;
    int gG  = (Nn + 127) / 128;
    int gE  = (Ee + TB - 1) / TB;
    int gNw = (Nn * 32 + TB - 1) / TB;       // warp per node

    // ---- layer 1 + CSR build ----
    k_gemm1<<<gG, TB>>>(x, W1, as1, ad1);    // also zeroes g_cnt
    k_hist<<<gE, TB>>>(dst);
    k_scan_block<<<SCB, 512>>>();
    k_scan_top<<<1, 32>>>();
    k_scan_add<<<SCB, 512>>>();
    k_fill<<<gE, TB>>>(src, dst);
    k_msg1<<<gNw, TB>>>();                   // gather-only, den fused, no atomics
    k_stats<<<(Nn + 63) / 64, 128>>>();      // fused: rinv(den1) + BN stats
    // ---- layer 2 (reuses CSR) ----
    k_gemm2<<<gG, TB>>>(W2, as2, ad2, gamma, beta);
    k_msg2<<<gNw, TB>>>();
    k_final2<<<gNw, TB>>>(b2, out);
}